// round 1
// baseline (speedup 1.0000x reference)
#include <cuda_runtime.h>
#include <cuda_bf16.h>

#define NN 50000
#define EE 800000
#define FN 128
#define FEG 8
#define HA 64
#define NH 8
#define PP 16

// ---------------- scratch (static device globals; no allocation) ----------
__device__ float g_prop_src[NN * FN];
__device__ float g_prop_dst[NN * FN];
__device__ float g_a_src[NN * NH];
__device__ float g_a_dst[NN * NH];
__device__ float g_att[EE * NH];
__device__ int   g_deg[NN];
__device__ int   g_off[NN];
__device__ int   g_cur[NN];
__device__ int   g_eid[EE];

// ---------------- K1: node MLPs ------------------------------------------
// block = 128 threads, NB=8 nodes per block. Thread t = output column.
#define NB 8
__global__ void __launch_bounds__(128) node_mlp_kernel(
    const float* __restrict__ feat,
    const float* __restrict__ wps, const float* __restrict__ bps,
    const float* __restrict__ wpd, const float* __restrict__ bpd,
    const float* __restrict__ was0, const float* __restrict__ was1,
    const float* __restrict__ wad0, const float* __restrict__ wad1)
{
    __shared__ __align__(16) float fs[NB][FN];
    __shared__ __align__(16) float hs[NB][HA];
    __shared__ __align__(16) float hd[NB][HA];

    int t = threadIdx.x;            // 0..127
    int n0 = blockIdx.x * NB;

    #pragma unroll
    for (int j = 0; j < NB; j++)
        fs[j][t] = feat[(n0 + j) * FN + t];
    __syncthreads();

    float aps[NB], apd[NB], as_[NB], ad_[NB];
    #pragma unroll
    for (int j = 0; j < NB; j++) { aps[j]=0.f; apd[j]=0.f; as_[j]=0.f; ad_[j]=0.f; }

    const bool att_lane = (t < HA);   // warp-uniform

    #pragma unroll 4
    for (int k = 0; k < FN; k++) {
        float w1 = wps[k * FN + t];
        float w2 = wpd[k * FN + t];
        #pragma unroll
        for (int j = 0; j < NB; j++) {
            float f = fs[j][k];
            aps[j] += f * w1;
            apd[j] += f * w2;
        }
        if (att_lane) {
            float w3 = was0[k * HA + t];
            float w4 = wad0[k * HA + t];
            #pragma unroll
            for (int j = 0; j < NB; j++) {
                float f = fs[j][k];
                as_[j] += f * w3;
                ad_[j] += f * w4;
            }
        }
    }

    float b1 = bps[t], b2 = bpd[t];
    #pragma unroll
    for (int j = 0; j < NB; j++) {
        g_prop_src[(n0 + j) * FN + t] = aps[j] + b1;
        g_prop_dst[(n0 + j) * FN + t] = apd[j] + b2;
    }
    if (att_lane) {
        #pragma unroll
        for (int j = 0; j < NB; j++) {
            hs[j][t] = fmaxf(as_[j], 0.f);
            hd[j][t] = fmaxf(ad_[j], 0.f);
        }
    }
    __syncthreads();

    // second layer: 8 nodes x 16 (8 src-heads + 8 dst-heads) = 128 outputs
    int j = t >> 4;
    int r = t & 15;
    if (r < NH) {
        float a = 0.f;
        #pragma unroll 8
        for (int k = 0; k < HA; k++) a += hs[j][k] * was1[k * NH + r];
        g_a_src[(n0 + j) * NH + r] = a;
    } else {
        int h = r - NH;
        float a = 0.f;
        #pragma unroll 8
        for (int k = 0; k < HA; k++) a += hd[j][k] * wad1[k * NH + h];
        g_a_dst[(n0 + j) * NH + h] = a;
    }
}

// ---------------- CSR build ----------------------------------------------
__global__ void zero_deg_kernel()
{
    int i = blockIdx.x * 256 + threadIdx.x;
    if (i < NN) g_deg[i] = 0;
}

__global__ void count_deg_kernel(const int* __restrict__ dst)
{
    int e = blockIdx.x * 256 + threadIdx.x;
    if (e < EE) atomicAdd(&g_deg[dst[e]], 1);
}

__global__ void __launch_bounds__(1024) scan_deg_kernel()
{
    __shared__ int s[1024];
    __shared__ int carry;
    int t = threadIdx.x;
    if (t == 0) carry = 0;
    __syncthreads();

    for (int base = 0; base < NN; base += 1024) {
        int i = base + t;
        int v = (i < NN) ? g_deg[i] : 0;
        s[t] = v;
        __syncthreads();
        #pragma unroll
        for (int o = 1; o < 1024; o <<= 1) {
            int tv = (t >= o) ? s[t - o] : 0;
            __syncthreads();
            s[t] += tv;
            __syncthreads();
        }
        int excl = s[t] - v;
        if (i < NN) {
            int off = carry + excl;
            g_off[i] = off;
            g_cur[i] = off;
        }
        int tot = s[1023];
        __syncthreads();
        if (t == 0) carry += tot;
        __syncthreads();
    }
}

__global__ void scatter_edges_kernel(const int* __restrict__ dst)
{
    int e = blockIdx.x * 256 + threadIdx.x;
    if (e < EE) {
        int p = atomicAdd(&g_cur[dst[e]], 1);
        g_eid[p] = e;
    }
}

// ---------------- K5: edge MLP + attention logits -------------------------
__global__ void __launch_bounds__(256) edge_att_kernel(
    const float* __restrict__ fe_g,
    const int* __restrict__ src, const int* __restrict__ dst,
    const float* __restrict__ we0, const float* __restrict__ we1)
{
    __shared__ __align__(16) float we0t[HA * FEG];  // [c][k] transposed
    __shared__ __align__(16) float we1s[HA * NH];   // [c][h]

    int t = threadIdx.x;
    #pragma unroll
    for (int i = t; i < HA * FEG; i += 256) {
        int c = i >> 3, k = i & 7;
        we0t[i] = we0[k * HA + c];
        we1s[i] = we1[i];
    }
    __syncthreads();

    int e = blockIdx.x * 256 + t;
    if (e >= EE) return;

    float4 f0 = reinterpret_cast<const float4*>(fe_g)[e * 2];
    float4 f1 = reinterpret_cast<const float4*>(fe_g)[e * 2 + 1];

    float a[NH];
    #pragma unroll
    for (int h = 0; h < NH; h++) a[h] = 0.f;

    #pragma unroll 4
    for (int c = 0; c < HA; c++) {
        float4 wa = reinterpret_cast<const float4*>(we0t + c * 8)[0];
        float4 wb = reinterpret_cast<const float4*>(we0t + c * 8)[1];
        float hsum = f0.x*wa.x + f0.y*wa.y + f0.z*wa.z + f0.w*wa.w
                   + f1.x*wb.x + f1.y*wb.y + f1.z*wb.z + f1.w*wb.w;
        hsum = fmaxf(hsum, 0.f);
        float4 va = reinterpret_cast<const float4*>(we1s + c * 8)[0];
        float4 vb = reinterpret_cast<const float4*>(we1s + c * 8)[1];
        a[0] += hsum * va.x; a[1] += hsum * va.y;
        a[2] += hsum * va.z; a[3] += hsum * va.w;
        a[4] += hsum * vb.x; a[5] += hsum * vb.y;
        a[6] += hsum * vb.z; a[7] += hsum * vb.w;
    }

    int s = src[e], d = dst[e];
    float4 s0 = reinterpret_cast<const float4*>(g_a_src)[s * 2];
    float4 s1 = reinterpret_cast<const float4*>(g_a_src)[s * 2 + 1];
    float4 d0 = reinterpret_cast<const float4*>(g_a_dst)[d * 2];
    float4 d1 = reinterpret_cast<const float4*>(g_a_dst)[d * 2 + 1];

    float4 o0, o1;
    o0.x = fmaxf(a[0] + s0.x + d0.x, 0.f);
    o0.y = fmaxf(a[1] + s0.y + d0.y, 0.f);
    o0.z = fmaxf(a[2] + s0.z + d0.z, 0.f);
    o0.w = fmaxf(a[3] + s0.w + d0.w, 0.f);
    o1.x = fmaxf(a[4] + s1.x + d1.x, 0.f);
    o1.y = fmaxf(a[5] + s1.y + d1.y, 0.f);
    o1.z = fmaxf(a[6] + s1.z + d1.z, 0.f);
    o1.w = fmaxf(a[7] + s1.w + d1.w, 0.f);
    reinterpret_cast<float4*>(g_att)[e * 2]     = o0;
    reinterpret_cast<float4*>(g_att)[e * 2 + 1] = o1;
}

// ---------------- K_final: per-dst softmax + aggregate + residual ---------
// one warp per destination node; lane l owns cols 4l..4l+3 (head l>>2)
__global__ void __launch_bounds__(256) softmax_agg_kernel(
    const int* __restrict__ src, float* __restrict__ out)
{
    int warp = threadIdx.x >> 5;
    int l    = threadIdx.x & 31;
    int n = blockIdx.x * 8 + warp;
    if (n >= NN) return;

    int start = g_off[n];
    int cnt   = g_deg[n];
    int h     = l >> 2;

    // pass 1: per-head max (att >= 0, so init 0 is exact)
    float m = 0.f;
    for (int j = 0; j < cnt; j++) {
        int e = g_eid[start + j];
        m = fmaxf(m, __ldg(&g_att[e * NH + h]));
    }

    // pass 2: fused exp-sum + weighted gather-accumulate
    float4 acc = make_float4(0.f, 0.f, 0.f, 0.f);
    float den = 0.f;
    for (int j = 0; j < cnt; j++) {
        int e = g_eid[start + j];
        float ex = __expf(__ldg(&g_att[e * NH + h]) - m);
        den += ex;
        int s = src[e];
        float4 p = reinterpret_cast<const float4*>(g_prop_src)[s * 32 + l];
        acc.x += ex * p.x;
        acc.y += ex * p.y;
        acc.z += ex * p.z;
        acc.w += ex * p.w;
    }

    float inv = 1.f / fmaxf(den, 1e-16f);
    float4 pd = reinterpret_cast<const float4*>(g_prop_dst)[n * 32 + l];
    float4 o;
    o.x = acc.x * inv + pd.x;
    o.y = acc.y * inv + pd.y;
    o.z = acc.z * inv + pd.z;
    o.w = acc.w * inv + pd.w;
    reinterpret_cast<float4*>(out)[n * 32 + l] = o;
}

// ---------------- launch ---------------------------------------------------
extern "C" void kernel_launch(void* const* d_in, const int* in_sizes, int n_in,
                              void* d_out, int out_size)
{
    const float* feat      = (const float*)d_in[0];
    const float* feat_edge = (const float*)d_in[1];
    const int*   src       = (const int*)  d_in[2];
    const int*   dst       = (const int*)  d_in[3];
    const float* was0      = (const float*)d_in[4];
    const float* was1      = (const float*)d_in[5];
    const float* wad0      = (const float*)d_in[6];
    const float* wad1      = (const float*)d_in[7];
    const float* we0       = (const float*)d_in[8];
    const float* we1       = (const float*)d_in[9];
    const float* wps       = (const float*)d_in[10];
    const float* bps       = (const float*)d_in[11];
    const float* wpd       = (const float*)d_in[12];
    const float* bpd       = (const float*)d_in[13];
    float* out = (float*)d_out;

    // CSR build (independent of MLPs; interleave for overlap on one stream)
    zero_deg_kernel<<<(NN + 255) / 256, 256>>>();
    count_deg_kernel<<<(EE + 255) / 256, 256>>>(dst);
    scan_deg_kernel<<<1, 1024>>>();
    scatter_edges_kernel<<<(EE + 255) / 256, 256>>>(dst);

    // node MLPs
    node_mlp_kernel<<<NN / NB, 128>>>(feat, wps, bps, wpd, bpd,
                                      was0, was1, wad0, wad1);

    // edge MLP + attention logits
    edge_att_kernel<<<(EE + 255) / 256, 256>>>(feat_edge, src, dst, we0, we1);

    // per-node softmax + aggregation + residual
    softmax_agg_kernel<<<(NN + 7) / 8, 256>>>(src, out);
}

// round 9
// speedup vs baseline: 1.2572x; 1.2572x over previous
#include <cuda_runtime.h>
#include <cuda_bf16.h>
#include <cstdint>

#define NN 50000
#define EE 800000
#define FN 128
#define HA 64
#define NH 8

// ---------------- scratch ----------------
__device__ float g_prop_src[NN * FN];
__device__ float g_prop_dst[NN * FN];
__device__ float g_hs[NN * HA];
__device__ float g_hd[NN * HA];
__device__ float g_a_src[NN * NH];
__device__ float g_a_dst[NN * NH];
__device__ float g_att[EE * NH];     // dst-sorted order
__device__ int   g_deg[NN];
__device__ int   g_off[NN];
__device__ int   g_cur[NN];
__device__ int   g_pos[EE];          // edge -> sorted slot
__device__ int   g_srcs[EE];         // src id in sorted order

// ================= K1: fused node GEMM (tf32 mma, 2-term split) ==========
// C[50000 x 384] = feat @ [wps | wpd | was0|wad0],  K = 128
// grid = (782, 3); block = 256 (8 warps: 4 m-warps x 2 n-warps)
// block tile: M=64, N=128, K chunked by 32.
#define MT 64
#define CH 32
#define AS 36    // A smem row stride (conflict-free frag loads)
#define BS 136   // B smem row stride

__device__ __forceinline__ uint32_t f2tf32(float x) {
    uint32_t r;
    asm("cvt.rna.tf32.f32 %0, %1;" : "=r"(r) : "f"(x));
    return r;
}
__device__ __forceinline__ void split_tf32(float x, uint32_t& hi, uint32_t& lo) {
    hi = f2tf32(x);
    float rem = x - __uint_as_float(hi);
    lo = f2tf32(rem);
}
__device__ __forceinline__ void mma_tf32(float* c, const uint32_t* a,
                                         uint32_t b0, uint32_t b1) {
    asm volatile(
        "mma.sync.aligned.m16n8k8.row.col.f32.tf32.tf32.f32 "
        "{%0,%1,%2,%3}, {%4,%5,%6,%7}, {%8,%9}, {%0,%1,%2,%3};"
        : "+f"(c[0]), "+f"(c[1]), "+f"(c[2]), "+f"(c[3])
        : "r"(a[0]), "r"(a[1]), "r"(a[2]), "r"(a[3]), "r"(b0), "r"(b1));
}

__global__ void __launch_bounds__(256) node_gemm_kernel(
    const float* __restrict__ feat,
    const float* __restrict__ wps, const float* __restrict__ bps,
    const float* __restrict__ wpd, const float* __restrict__ bpd,
    const float* __restrict__ was0, const float* __restrict__ wad0)
{
    extern __shared__ uint32_t sm[];
    uint32_t* sAh = sm;                      // 64*36
    uint32_t* sAl = sAh + MT * AS;
    uint32_t* sBh = sAl + MT * AS;           // 32*136
    uint32_t* sBl = sBh + CH * BS;

    const int tid = threadIdx.x;
    const int m0 = blockIdx.x * MT;
    const int nb = blockIdx.y;               // 0: wps, 1: wpd, 2: [was0|wad0]

    const int wid = tid >> 5;
    const int lane = tid & 31;
    const int warp_m = wid & 3;              // 0..3  -> m offset *16
    const int warp_n = wid >> 2;             // 0..1  -> n offset *64
    const int gid = lane >> 2;               // 0..7
    const int tig = lane & 3;                // 0..3
    const int m_w = warp_m * 16;
    const int n_w = warp_n * 64;

    float acc[8][4];
    #pragma unroll
    for (int j = 0; j < 8; j++)
        #pragma unroll
        for (int i = 0; i < 4; i++) acc[j][i] = 0.f;

    for (int kc = 0; kc < FN; kc += CH) {
        // ---- stage A: feat[m0..m0+63][kc..kc+31] -> hi/lo tf32
        #pragma unroll
        for (int p = 0; p < 2; p++) {
            int idx = tid + p * 256;          // 0..511  (64 rows x 8 float4)
            int row = idx >> 3;
            int q = (idx & 7) * 4;
            int node = m0 + row;
            float4 v = make_float4(0.f, 0.f, 0.f, 0.f);
            if (node < NN)
                v = *reinterpret_cast<const float4*>(&feat[node * FN + kc + q]);
            uint32_t h, l;
            int base = row * AS + q;
            split_tf32(v.x, h, l); sAh[base    ] = h; sAl[base    ] = l;
            split_tf32(v.y, h, l); sAh[base + 1] = h; sAl[base + 1] = l;
            split_tf32(v.z, h, l); sAh[base + 2] = h; sAl[base + 2] = l;
            split_tf32(v.w, h, l); sAh[base + 3] = h; sAl[base + 3] = l;
        }
        // ---- stage B: W[kc..kc+31][0..127] for this nb
        #pragma unroll
        for (int p = 0; p < 4; p++) {
            int idx = tid + p * 256;          // 0..1023 (32 rows x 32 float4)
            int row = idx >> 5;
            int q = (idx & 31) * 4;
            int k = kc + row;
            float4 v;
            if (nb == 0)
                v = *reinterpret_cast<const float4*>(&wps[k * FN + q]);
            else if (nb == 1)
                v = *reinterpret_cast<const float4*>(&wpd[k * FN + q]);
            else {
                if (q < 64)
                    v = *reinterpret_cast<const float4*>(&was0[k * HA + q]);
                else
                    v = *reinterpret_cast<const float4*>(&wad0[k * HA + q - 64]);
            }
            uint32_t h, l;
            int base = row * BS + q;
            split_tf32(v.x, h, l); sBh[base    ] = h; sBl[base    ] = l;
            split_tf32(v.y, h, l); sBh[base + 1] = h; sBl[base + 1] = l;
            split_tf32(v.z, h, l); sBh[base + 2] = h; sBl[base + 2] = l;
            split_tf32(v.w, h, l); sBh[base + 3] = h; sBl[base + 3] = l;
        }
        __syncthreads();

        // ---- mma over 4 k-steps of 8
        #pragma unroll
        for (int ks = 0; ks < 4; ks++) {
            int kk = ks * 8;
            int abase = (m_w + gid) * AS + kk + tig;
            uint32_t ah[4], al[4];
            ah[0] = sAh[abase];              al[0] = sAl[abase];
            ah[1] = sAh[abase + 8 * AS];     al[1] = sAl[abase + 8 * AS];
            ah[2] = sAh[abase + 4];          al[2] = sAl[abase + 4];
            ah[3] = sAh[abase + 8 * AS + 4]; al[3] = sAl[abase + 8 * AS + 4];
            #pragma unroll
            for (int j = 0; j < 8; j++) {
                int bcol = n_w + j * 8 + gid;
                int b0i = (kk + tig) * BS + bcol;
                uint32_t bh0 = sBh[b0i], bh1 = sBh[b0i + 4 * BS];
                uint32_t bl0 = sBl[b0i], bl1 = sBl[b0i + 4 * BS];
                mma_tf32(acc[j], ah, bh0, bh1);   // hi*hi
                mma_tf32(acc[j], ah, bl0, bl1);   // hi*lo
                mma_tf32(acc[j], al, bh0, bh1);   // lo*hi
            }
        }
        __syncthreads();
    }

    // ---- epilogue
    #pragma unroll
    for (int half = 0; half < 2; half++) {
        int node = m0 + m_w + gid + half * 8;
        if (node >= NN) continue;
        #pragma unroll
        for (int j = 0; j < 8; j++) {
            int col = n_w + j * 8 + tig * 2;
            float v0 = acc[j][half * 2 + 0];
            float v1 = acc[j][half * 2 + 1];
            if (nb == 0) {
                g_prop_src[node * FN + col]     = v0 + bps[col];
                g_prop_src[node * FN + col + 1] = v1 + bps[col + 1];
            } else if (nb == 1) {
                g_prop_dst[node * FN + col]     = v0 + bpd[col];
                g_prop_dst[node * FN + col + 1] = v1 + bpd[col + 1];
            } else if (warp_n == 0) {
                g_hs[node * HA + col]     = fmaxf(v0, 0.f);
                g_hs[node * HA + col + 1] = fmaxf(v1, 0.f);
            } else {
                g_hd[node * HA + col - 64]     = fmaxf(v0, 0.f);
                g_hd[node * HA + col - 63]     = fmaxf(v1, 0.f);
            }
        }
    }
}

// ================= K2: attention second layer ============================
#define NB2 8
__global__ void __launch_bounds__(128) att_layer2_kernel(
    const float* __restrict__ was1, const float* __restrict__ wad1)
{
    __shared__ __align__(16) float hs[NB2][HA];
    __shared__ __align__(16) float hd[NB2][HA];
    int t = threadIdx.x;
    int n0 = blockIdx.x * NB2;

    #pragma unroll
    for (int p = 0; p < 4; p++) {
        int idx = t + p * 128;               // 0..511
        int j = idx >> 6, c = idx & 63;
        hs[j][c] = g_hs[(n0 + j) * HA + c];
        hd[j][c] = g_hd[(n0 + j) * HA + c];
    }
    __syncthreads();

    int j = t >> 4, r = t & 15;
    if (r < NH) {
        float a = 0.f;
        #pragma unroll 8
        for (int k = 0; k < HA; k++) a += hs[j][k] * was1[k * NH + r];
        g_a_src[(n0 + j) * NH + r] = a;
    } else {
        int h = r - NH;
        float a = 0.f;
        #pragma unroll 8
        for (int k = 0; k < HA; k++) a += hd[j][k] * wad1[k * NH + h];
        g_a_dst[(n0 + j) * NH + h] = a;
    }
}

// ================= CSR build =============================================
__global__ void zero_deg_kernel()
{
    int i = blockIdx.x * 256 + threadIdx.x;
    if (i < NN) g_deg[i] = 0;
}

__global__ void count_deg_kernel(const int* __restrict__ dst)
{
    int e = blockIdx.x * 256 + threadIdx.x;
    if (e < EE) atomicAdd(&g_deg[dst[e]], 1);
}

// thread-coarsened single-block scan: 1024 thr x 49 elems
__global__ void __launch_bounds__(1024) scan_deg_kernel()
{
    __shared__ int wsums[32];
    const int C = 49;
    int t = threadIdx.x;
    int lane = t & 31, wid = t >> 5;
    int begin = t * C;

    int s = 0;
    for (int i = 0; i < C; i++) {
        int idx = begin + i;
        if (idx < NN) s += g_deg[idx];
    }
    int incl = s;
    #pragma unroll
    for (int o = 1; o < 32; o <<= 1) {
        int v = __shfl_up_sync(0xffffffff, incl, o);
        if (lane >= o) incl += v;
    }
    if (lane == 31) wsums[wid] = incl;
    __syncthreads();
    if (wid == 0) {
        int w = wsums[lane];
        int wi = w;
        #pragma unroll
        for (int o = 1; o < 32; o <<= 1) {
            int v = __shfl_up_sync(0xffffffff, wi, o);
            if (lane >= o) wi += v;
        }
        wsums[lane] = wi - w;                // exclusive warp base
    }
    __syncthreads();

    int run = wsums[wid] + incl - s;         // exclusive prefix for this thread
    for (int i = 0; i < C; i++) {
        int idx = begin + i;
        if (idx < NN) {
            g_off[idx] = run;
            g_cur[idx] = run;
            run += g_deg[idx];
        }
    }
}

__global__ void scatter_edges_kernel(const int* __restrict__ src,
                                     const int* __restrict__ dst)
{
    int e = blockIdx.x * 256 + threadIdx.x;
    if (e < EE) {
        int p = atomicAdd(&g_cur[dst[e]], 1);
        g_pos[e] = p;
        g_srcs[p] = src[e];
    }
}

// ================= K5: edge MLP + attention logits (write sorted) =========
#define FEG 8
__global__ void __launch_bounds__(256) edge_att_kernel(
    const float* __restrict__ fe_g,
    const int* __restrict__ src, const int* __restrict__ dst,
    const float* __restrict__ we0, const float* __restrict__ we1)
{
    __shared__ __align__(16) float we0t[HA * FEG];  // [c][k]
    __shared__ __align__(16) float we1s[HA * NH];   // [c][h]

    int t = threadIdx.x;
    #pragma unroll
    for (int i = t; i < HA * FEG; i += 256) {
        int c = i >> 3, k = i & 7;
        we0t[i] = we0[k * HA + c];
        we1s[i] = we1[i];
    }
    __syncthreads();

    int e = blockIdx.x * 256 + t;
    if (e >= EE) return;

    float4 f0 = reinterpret_cast<const float4*>(fe_g)[e * 2];
    float4 f1 = reinterpret_cast<const float4*>(fe_g)[e * 2 + 1];

    float a[NH];
    #pragma unroll
    for (int h = 0; h < NH; h++) a[h] = 0.f;

    #pragma unroll 4
    for (int c = 0; c < HA; c++) {
        float4 wa = reinterpret_cast<const float4*>(we0t + c * 8)[0];
        float4 wb = reinterpret_cast<const float4*>(we0t + c * 8)[1];
        float hsum = f0.x*wa.x + f0.y*wa.y + f0.z*wa.z + f0.w*wa.w
                   + f1.x*wb.x + f1.y*wb.y + f1.z*wb.z + f1.w*wb.w;
        hsum = fmaxf(hsum, 0.f);
        float4 va = reinterpret_cast<const float4*>(we1s + c * 8)[0];
        float4 vb = reinterpret_cast<const float4*>(we1s + c * 8)[1];
        a[0] += hsum * va.x; a[1] += hsum * va.y;
        a[2] += hsum * va.z; a[3] += hsum * va.w;
        a[4] += hsum * vb.x; a[5] += hsum * vb.y;
        a[6] += hsum * vb.z; a[7] += hsum * vb.w;
    }

    int s = src[e], d = dst[e];
    float4 s0 = reinterpret_cast<const float4*>(g_a_src)[s * 2];
    float4 s1 = reinterpret_cast<const float4*>(g_a_src)[s * 2 + 1];
    float4 d0 = reinterpret_cast<const float4*>(g_a_dst)[d * 2];
    float4 d1 = reinterpret_cast<const float4*>(g_a_dst)[d * 2 + 1];

    float4 o0, o1;
    o0.x = fmaxf(a[0] + s0.x + d0.x, 0.f);
    o0.y = fmaxf(a[1] + s0.y + d0.y, 0.f);
    o0.z = fmaxf(a[2] + s0.z + d0.z, 0.f);
    o0.w = fmaxf(a[3] + s0.w + d0.w, 0.f);
    o1.x = fmaxf(a[4] + s1.x + d1.x, 0.f);
    o1.y = fmaxf(a[5] + s1.y + d1.y, 0.f);
    o1.z = fmaxf(a[6] + s1.z + d1.z, 0.f);
    o1.w = fmaxf(a[7] + s1.w + d1.w, 0.f);

    int p = g_pos[e];
    reinterpret_cast<float4*>(g_att)[p * 2]     = o0;
    reinterpret_cast<float4*>(g_att)[p * 2 + 1] = o1;
}

// ================= K6: single-pass softmax + aggregate + residual =========
// one warp per dst node; lane l owns cols 4l..4l+3 (head l>>2)
// softmax computed WITHOUT max-shift: att >= 0 and bounded (~15), exp safe;
// mathematically identical to the max-shifted form.
__global__ void __launch_bounds__(256) softmax_agg_kernel(float* __restrict__ out)
{
    int warp = threadIdx.x >> 5;
    int l    = threadIdx.x & 31;
    int n = blockIdx.x * 8 + warp;
    if (n >= NN) return;

    int start = g_off[n];
    int cnt   = g_deg[n];
    int h     = l >> 2;

    float4 acc = make_float4(0.f, 0.f, 0.f, 0.f);
    float den = 0.f;
    for (int j = 0; j < cnt; j++) {
        int p = start + j;
        float ex = __expf(__ldg(&g_att[p * NH + h]));
        den += ex;
        int s = g_srcs[p];
        float4 v = reinterpret_cast<const float4*>(g_prop_src)[s * 32 + l];
        acc.x += ex * v.x;
        acc.y += ex * v.y;
        acc.z += ex * v.z;
        acc.w += ex * v.w;
    }

    float inv = 1.f / fmaxf(den, 1e-16f);
    float4 pd = reinterpret_cast<const float4*>(g_prop_dst)[n * 32 + l];
    float4 o;
    o.x = acc.x * inv + pd.x;
    o.y = acc.y * inv + pd.y;
    o.z = acc.z * inv + pd.z;
    o.w = acc.w * inv + pd.w;
    reinterpret_cast<float4*>(out)[n * 32 + l] = o;
}

// ================= launch ================================================
extern "C" void kernel_launch(void* const* d_in, const int* in_sizes, int n_in,
                              void* d_out, int out_size)
{
    const float* feat      = (const float*)d_in[0];
    const float* feat_edge = (const float*)d_in[1];
    const int*   src       = (const int*)  d_in[2];
    const int*   dst       = (const int*)  d_in[3];
    const float* was0      = (const float*)d_in[4];
    const float* was1      = (const float*)d_in[5];
    const float* wad0      = (const float*)d_in[6];
    const float* wad1      = (const float*)d_in[7];
    const float* we0       = (const float*)d_in[8];
    const float* we1       = (const float*)d_in[9];
    const float* wps       = (const float*)d_in[10];
    const float* bps       = (const float*)d_in[11];
    const float* wpd       = (const float*)d_in[12];
    const float* bpd       = (const float*)d_in[13];
    float* out = (float*)d_out;

    // non-stream API: safe under graph capture, called unconditionally
    const int smem_gemm = (2 * MT * AS + 2 * CH * BS) * 4;  // 53248 B
    cudaFuncSetAttribute(node_gemm_kernel,
                         cudaFuncAttributeMaxDynamicSharedMemorySize,
                         smem_gemm);

    // CSR build
    zero_deg_kernel<<<(NN + 255) / 256, 256>>>();
    count_deg_kernel<<<(EE + 255) / 256, 256>>>(dst);
    scan_deg_kernel<<<1, 1024>>>();
    scatter_edges_kernel<<<(EE + 255) / 256, 256>>>(src, dst);

    // fused node GEMM (tensor cores) + attention layer 2
    node_gemm_kernel<<<dim3((NN + MT - 1) / MT, 3), 256, smem_gemm>>>(
        feat, wps, bps, wpd, bpd, was0, wad0);
    att_layer2_kernel<<<NN / NB2, 128>>>(was1, wad1);

    // edge MLP + logits (written in CSR order)
    edge_att_kernel<<<(EE + 255) / 256, 256>>>(feat_edge, src, dst, we0, we1);

    // single-pass softmax + aggregation + residual
    softmax_agg_kernel<<<(NN + 7) / 8, 256>>>(out);
}